// round 2
// baseline (speedup 1.0000x reference)
#include <cuda_runtime.h>
#include <math.h>

#define TOK_MAX 16384
#define NEXP 256
#define KDIM 7168
#define BM 128
#define BN 128
#define BK 16
#define NSPLIT 8
#define KSPLIT (KDIM / NSPLIT)   // 896
#define SPAD 132                 // BM + 4, multiple of 4

// Split-K partial logits: [T][NSPLIT][256]  (134 MB)
__device__ float g_part[(size_t)TOK_MAX * NSPLIT * NEXP];

// ---------------------------------------------------------------------------
// SGEMM split-K: partial[t, z, e] = sum_{k in split z} X[t,k] * W[e,k]
// ---------------------------------------------------------------------------
__global__ __launch_bounds__(256, 2)
void gate_gemm_kernel(const float* __restrict__ X,
                      const float* __restrict__ W) {
    __shared__ __align__(16) float As[2][BK][SPAD];
    __shared__ __align__(16) float Bs[2][BK][SPAD];

    const int tid = threadIdx.x;
    const int bm = blockIdx.x;      // token tile
    const int bn = blockIdx.y;      // expert tile (0..1)
    const int bz = blockIdx.z;      // k split (0..7)

    const float* Ablk = X + (size_t)bm * BM * KDIM + (size_t)bz * KSPLIT;
    const float* Bblk = W + (size_t)bn * BN * KDIM + (size_t)bz * KSPLIT;

    const int lr = tid >> 2;         // 0..63
    const int lc = (tid & 3) << 2;   // 0,4,8,12

    const int ty = (tid >> 4) << 3;  // 0..120
    const int tx = (tid & 15) << 3;  // 0..120

    float acc[8][8];
    #pragma unroll
    for (int i = 0; i < 8; i++)
        #pragma unroll
        for (int j = 0; j < 8; j++) acc[i][j] = 0.0f;

    float4 pa[2], pb[2];

    #pragma unroll
    for (int i = 0; i < 2; i++) {
        int r = lr + i * 64;
        pa[i] = *(const float4*)(Ablk + (size_t)r * KDIM + lc);
        pb[i] = *(const float4*)(Bblk + (size_t)r * KDIM + lc);
    }
    #pragma unroll
    for (int i = 0; i < 2; i++) {
        int r = lr + i * 64;
        As[0][lc + 0][r] = pa[i].x; As[0][lc + 1][r] = pa[i].y;
        As[0][lc + 2][r] = pa[i].z; As[0][lc + 3][r] = pa[i].w;
        Bs[0][lc + 0][r] = pb[i].x; Bs[0][lc + 1][r] = pb[i].y;
        Bs[0][lc + 2][r] = pb[i].z; Bs[0][lc + 3][r] = pb[i].w;
    }
    __syncthreads();

    const int nk = KSPLIT / BK;  // 56
    for (int kt = 0; kt < nk; kt++) {
        const int buf = kt & 1;
        if (kt + 1 < nk) {
            const int koff = (kt + 1) * BK + lc;
            #pragma unroll
            for (int i = 0; i < 2; i++) {
                int r = lr + i * 64;
                pa[i] = *(const float4*)(Ablk + (size_t)r * KDIM + koff);
                pb[i] = *(const float4*)(Bblk + (size_t)r * KDIM + koff);
            }
        }
        #pragma unroll
        for (int k = 0; k < BK; k++) {
            float4 a0 = *(const float4*)&As[buf][k][ty];
            float4 a1 = *(const float4*)&As[buf][k][ty + 4];
            float4 b0 = *(const float4*)&Bs[buf][k][tx];
            float4 b1 = *(const float4*)&Bs[buf][k][tx + 4];
            float a[8] = {a0.x, a0.y, a0.z, a0.w, a1.x, a1.y, a1.z, a1.w};
            float b[8] = {b0.x, b0.y, b0.z, b0.w, b1.x, b1.y, b1.z, b1.w};
            #pragma unroll
            for (int i = 0; i < 8; i++)
                #pragma unroll
                for (int j = 0; j < 8; j++)
                    acc[i][j] = fmaf(a[i], b[j], acc[i][j]);
        }
        if (kt + 1 < nk) {
            const int nbuf = 1 - buf;
            #pragma unroll
            for (int i = 0; i < 2; i++) {
                int r = lr + i * 64;
                As[nbuf][lc + 0][r] = pa[i].x; As[nbuf][lc + 1][r] = pa[i].y;
                As[nbuf][lc + 2][r] = pa[i].z; As[nbuf][lc + 3][r] = pa[i].w;
                Bs[nbuf][lc + 0][r] = pb[i].x; Bs[nbuf][lc + 1][r] = pb[i].y;
                Bs[nbuf][lc + 2][r] = pb[i].z; Bs[nbuf][lc + 3][r] = pb[i].w;
            }
        }
        __syncthreads();
    }

    // epilogue: write partials [t][z][e]
    const int row0 = bm * BM + ty;
    const int col0 = bn * BN + tx;
    #pragma unroll
    for (int i = 0; i < 8; i++) {
        float* crow = g_part + (size_t)(row0 + i) * (NSPLIT * NEXP)
                             + (size_t)bz * NEXP + col0;
        #pragma unroll
        for (int j = 0; j < 8; j += 4) {
            float4 v = make_float4(acc[i][j], acc[i][j + 1], acc[i][j + 2], acc[i][j + 3]);
            *(float4*)(crow + j) = v;
        }
    }
}

// ---------------------------------------------------------------------------
// Reduce + routing: one warp per token.
// lane handles experts [lane*8, lane*8+8) -> group = lane/4.
// ---------------------------------------------------------------------------
__global__ void gate_route_kernel(const float* __restrict__ bias,
                                  float* __restrict__ out_w,
                                  float* __restrict__ out_i,
                                  int Tn) {
    const int warp = (blockIdx.x * blockDim.x + threadIdx.x) >> 5;
    if (warp >= Tn) return;
    const int lane = threadIdx.x & 31;
    const unsigned FULL = 0xffffffffu;

    const float* row = g_part + (size_t)warp * (NSPLIT * NEXP);

    // pairwise tree-reduce the 8 split partials for my 8 experts
    float p[8][8];   // p[z][j]
    #pragma unroll
    for (int z = 0; z < NSPLIT; z++) {
        float4 v0 = *(const float4*)(row + z * NEXP + lane * 8);
        float4 v1 = *(const float4*)(row + z * NEXP + lane * 8 + 4);
        p[z][0] = v0.x; p[z][1] = v0.y; p[z][2] = v0.z; p[z][3] = v0.w;
        p[z][4] = v1.x; p[z][5] = v1.y; p[z][6] = v1.z; p[z][7] = v1.w;
    }

    float sc[8], sb[8];
    #pragma unroll
    for (int j = 0; j < 8; j++) {
        float s01 = p[0][j] + p[1][j];
        float s23 = p[2][j] + p[3][j];
        float s45 = p[4][j] + p[5][j];
        float s67 = p[6][j] + p[7][j];
        float z = (s01 + s23) + (s45 + s67);
        float s = 1.0f / (1.0f + expf(-z));
        sc[j] = s;                       // original score (weights)
        sb[j] = s + bias[lane * 8 + j];  // biased score (selection)
    }

    // per-lane top-2 of biased scores
    float m1 = -INFINITY, m2 = -INFINITY;
    #pragma unroll
    for (int j = 0; j < 8; j++) {
        float v = sb[j];
        if (v > m1) { m2 = m1; m1 = v; }
        else if (v > m2) { m2 = v; }
    }
    // merge top-2 across the 4 lanes of this group
    #pragma unroll
    for (int off = 1; off <= 2; off <<= 1) {
        float o1 = __shfl_xor_sync(FULL, m1, off);
        float o2 = __shfl_xor_sync(FULL, m2, off);
        if (o1 > m1) { m2 = fmaxf(m1, o2); m1 = o1; }
        else         { m2 = fmaxf(m2, o1); }
    }
    float gsum = m1 + m2;  // group score

    float gs[8];
    #pragma unroll
    for (int g = 0; g < 8; g++) gs[g] = __shfl_sync(FULL, gsum, g * 4);

    // top-4 groups (stable: smaller group index wins ties)
    int chosen = 0;
    #pragma unroll
    for (int it = 0; it < 4; it++) {
        float best = -INFINITY; int bg = 0;
        #pragma unroll
        for (int g = 0; g < 8; g++) {
            if (!((chosen >> g) & 1) && gs[g] > best) { best = gs[g]; bg = g; }
        }
        chosen |= 1 << bg;
    }
    const bool kept = (chosen >> (lane >> 2)) & 1;

    float v[8];
    #pragma unroll
    for (int j = 0; j < 8; j++) v[j] = kept ? sb[j] : -INFINITY;

    float my_w = 0.0f; int my_i = 0;
    float wsum = 0.0f;

    #pragma unroll
    for (int it = 0; it < 8; it++) {
        float bv = -INFINITY; int bi = 0x7fffffff; float bsco = 0.0f;
        #pragma unroll
        for (int j = 0; j < 8; j++) {
            if (v[j] > bv) { bv = v[j]; bi = lane * 8 + j; bsco = sc[j]; }
        }
        #pragma unroll
        for (int off = 16; off; off >>= 1) {
            float ov = __shfl_xor_sync(FULL, bv, off);
            int   oi = __shfl_xor_sync(FULL, bi, off);
            float os = __shfl_xor_sync(FULL, bsco, off);
            if (ov > bv || (ov == bv && oi < bi)) { bv = ov; bi = oi; bsco = os; }
        }
        if (lane == it) { my_w = bsco; my_i = bi; }
        if ((bi >> 3) == lane) v[bi & 7] = -INFINITY;
        wsum += bsco;   // slot order, matches reference sum order
    }

    if (lane < 8) {
        out_w[(size_t)warp * 8 + lane] = (my_w / wsum) * 2.5f;
        out_i[(size_t)warp * 8 + lane] = (float)my_i;
    }
}

// ---------------------------------------------------------------------------
extern "C" void kernel_launch(void* const* d_in, const int* in_sizes, int n_in,
                              void* d_out, int out_size) {
    const float* x    = (const float*)d_in[0];   // [T, 7168]
    const float* w    = (const float*)d_in[1];   // [256, 7168]
    const float* bias = (const float*)d_in[2];   // [256]

    const int Tn = in_sizes[0] / KDIM;

    dim3 grid(Tn / BM, NEXP / BN, NSPLIT);
    gate_gemm_kernel<<<grid, 256>>>(x, w);

    float* out_w = (float*)d_out;                     // [T, 8] weights
    float* out_i = (float*)d_out + (size_t)Tn * 8;    // [T, 8] indices (as f32)

    const int warps_per_block = 8;
    const int blocks = (Tn + warps_per_block - 1) / warps_per_block;
    gate_route_kernel<<<blocks, warps_per_block * 32>>>(bias, out_w, out_i, Tn);
}

// round 3
// speedup vs baseline: 1.3892x; 1.3892x over previous
#include <cuda_runtime.h>
#include <math.h>

#define TOK_MAX 16384
#define NEXP 256
#define KDIM 7168
#define BM 128
#define BN 128
#define BK 16
#define NSPLIT 8
#define KSPLIT (KDIM / NSPLIT)   // 896
#define SPAD 132                 // BM + 4, multiple of 4

// Split-K partial logits: [T][NSPLIT][256]  (134 MB)
__device__ float g_part[(size_t)TOK_MAX * NSPLIT * NEXP];

// packed-pair fp32 helpers (Blackwell f32x2 pipe)
union F2 { float2 f; unsigned long long u; };

__device__ __forceinline__ void ffma2(F2& d, const F2& a, const F2& b) {
    asm("fma.rn.f32x2 %0, %1, %2, %0;" : "+l"(d.u) : "l"(a.u), "l"(b.u));
}
__device__ __forceinline__ F2 bcast2(float v) {
    F2 r;
    asm("mov.b64 %0, {%1, %1};" : "=l"(r.u) : "f"(v));
    return r;
}

// ---------------------------------------------------------------------------
// SGEMM split-K: partial[t, z, e] = sum_{k in split z} X[t,k] * W[e,k]
// Inner loop uses fma.rn.f32x2 (2 fp32 FMAs per instruction).
// ---------------------------------------------------------------------------
__global__ __launch_bounds__(256, 2)
void gate_gemm_kernel(const float* __restrict__ X,
                      const float* __restrict__ W) {
    __shared__ __align__(16) float As[2][BK][SPAD];
    __shared__ __align__(16) float Bs[2][BK][SPAD];

    const int tid = threadIdx.x;
    const int bm = blockIdx.x;      // token tile
    const int bn = blockIdx.y;      // expert tile (0..1)
    const int bz = blockIdx.z;      // k split (0..7)

    const float* Ablk = X + (size_t)bm * BM * KDIM + (size_t)bz * KSPLIT;
    const float* Bblk = W + (size_t)bn * BN * KDIM + (size_t)bz * KSPLIT;

    const int lr = tid >> 2;         // 0..63
    const int lc = (tid & 3) << 2;   // 0,4,8,12

    const int ty = (tid >> 4) << 3;  // 0..120 (row offset, 8 rows)
    const int tx = (tid & 15) << 3;  // 0..120 (col offset, 8 cols)

    // acc2[i2][j]: pair (row ty+2*i2, row ty+2*i2+1) x col tx+j
    F2 acc2[4][8];
    #pragma unroll
    for (int i = 0; i < 4; i++)
        #pragma unroll
        for (int j = 0; j < 8; j++) { acc2[i][j].f.x = 0.0f; acc2[i][j].f.y = 0.0f; }

    float4 pa[2], pb[2];

    #pragma unroll
    for (int i = 0; i < 2; i++) {
        int r = lr + i * 64;
        pa[i] = *(const float4*)(Ablk + (size_t)r * KDIM + lc);
        pb[i] = *(const float4*)(Bblk + (size_t)r * KDIM + lc);
    }
    #pragma unroll
    for (int i = 0; i < 2; i++) {
        int r = lr + i * 64;
        As[0][lc + 0][r] = pa[i].x; As[0][lc + 1][r] = pa[i].y;
        As[0][lc + 2][r] = pa[i].z; As[0][lc + 3][r] = pa[i].w;
        Bs[0][lc + 0][r] = pb[i].x; Bs[0][lc + 1][r] = pb[i].y;
        Bs[0][lc + 2][r] = pb[i].z; Bs[0][lc + 3][r] = pb[i].w;
    }
    __syncthreads();

    const int nk = KSPLIT / BK;  // 56
    for (int kt = 0; kt < nk; kt++) {
        const int buf = kt & 1;
        if (kt + 1 < nk) {
            const int koff = (kt + 1) * BK + lc;
            #pragma unroll
            for (int i = 0; i < 2; i++) {
                int r = lr + i * 64;
                pa[i] = *(const float4*)(Ablk + (size_t)r * KDIM + koff);
                pb[i] = *(const float4*)(Bblk + (size_t)r * KDIM + koff);
            }
        }
        #pragma unroll
        for (int k = 0; k < BK; k++) {
            // a pairs: contiguous rows in As
            F2 a2[4];
            #pragma unroll
            for (int i = 0; i < 4; i++)
                a2[i].f = *(const float2*)&As[buf][k][ty + 2 * i];
            // b broadcast pairs
            float4 b0 = *(const float4*)&Bs[buf][k][tx];
            float4 b1 = *(const float4*)&Bs[buf][k][tx + 4];
            F2 bb[8];
            bb[0] = bcast2(b0.x); bb[1] = bcast2(b0.y);
            bb[2] = bcast2(b0.z); bb[3] = bcast2(b0.w);
            bb[4] = bcast2(b1.x); bb[5] = bcast2(b1.y);
            bb[6] = bcast2(b1.z); bb[7] = bcast2(b1.w);
            #pragma unroll
            for (int i = 0; i < 4; i++)
                #pragma unroll
                for (int j = 0; j < 8; j++)
                    ffma2(acc2[i][j], a2[i], bb[j]);
        }
        if (kt + 1 < nk) {
            const int nbuf = 1 - buf;
            #pragma unroll
            for (int i = 0; i < 2; i++) {
                int r = lr + i * 64;
                As[nbuf][lc + 0][r] = pa[i].x; As[nbuf][lc + 1][r] = pa[i].y;
                As[nbuf][lc + 2][r] = pa[i].z; As[nbuf][lc + 3][r] = pa[i].w;
                Bs[nbuf][lc + 0][r] = pb[i].x; Bs[nbuf][lc + 1][r] = pb[i].y;
                Bs[nbuf][lc + 2][r] = pb[i].z; Bs[nbuf][lc + 3][r] = pb[i].w;
            }
        }
        __syncthreads();
    }

    // epilogue: write partials [t][z][e]
    const int row0 = bm * BM + ty;
    const int col0 = bn * BN + tx;
    #pragma unroll
    for (int i2 = 0; i2 < 4; i2++) {
        float* r0 = g_part + (size_t)(row0 + 2 * i2)     * (NSPLIT * NEXP) + (size_t)bz * NEXP + col0;
        float* r1 = g_part + (size_t)(row0 + 2 * i2 + 1) * (NSPLIT * NEXP) + (size_t)bz * NEXP + col0;
        #pragma unroll
        for (int j = 0; j < 8; j += 4) {
            float4 v0 = make_float4(acc2[i2][j].f.x, acc2[i2][j + 1].f.x,
                                    acc2[i2][j + 2].f.x, acc2[i2][j + 3].f.x);
            float4 v1 = make_float4(acc2[i2][j].f.y, acc2[i2][j + 1].f.y,
                                    acc2[i2][j + 2].f.y, acc2[i2][j + 3].f.y);
            *(float4*)(r0 + j) = v0;
            *(float4*)(r1 + j) = v1;
        }
    }
}

// ---------------------------------------------------------------------------
// Reduce + routing: one warp per token.
// lane handles experts [lane*8, lane*8+8) -> group = lane/4.
// ---------------------------------------------------------------------------
__global__ void gate_route_kernel(const float* __restrict__ bias,
                                  float* __restrict__ out_w,
                                  float* __restrict__ out_i,
                                  int Tn) {
    const int warp = (blockIdx.x * blockDim.x + threadIdx.x) >> 5;
    if (warp >= Tn) return;
    const int lane = threadIdx.x & 31;
    const unsigned FULL = 0xffffffffu;

    const float* row = g_part + (size_t)warp * (NSPLIT * NEXP);

    float p[8][8];   // p[z][j]
    #pragma unroll
    for (int z = 0; z < NSPLIT; z++) {
        float4 v0 = *(const float4*)(row + z * NEXP + lane * 8);
        float4 v1 = *(const float4*)(row + z * NEXP + lane * 8 + 4);
        p[z][0] = v0.x; p[z][1] = v0.y; p[z][2] = v0.z; p[z][3] = v0.w;
        p[z][4] = v1.x; p[z][5] = v1.y; p[z][6] = v1.z; p[z][7] = v1.w;
    }

    float sc[8], sb[8];
    #pragma unroll
    for (int j = 0; j < 8; j++) {
        float s01 = p[0][j] + p[1][j];
        float s23 = p[2][j] + p[3][j];
        float s45 = p[4][j] + p[5][j];
        float s67 = p[6][j] + p[7][j];
        float z = (s01 + s23) + (s45 + s67);
        float s = 1.0f / (1.0f + expf(-z));
        sc[j] = s;
        sb[j] = s + bias[lane * 8 + j];
    }

    float m1 = -INFINITY, m2 = -INFINITY;
    #pragma unroll
    for (int j = 0; j < 8; j++) {
        float v = sb[j];
        if (v > m1) { m2 = m1; m1 = v; }
        else if (v > m2) { m2 = v; }
    }
    #pragma unroll
    for (int off = 1; off <= 2; off <<= 1) {
        float o1 = __shfl_xor_sync(FULL, m1, off);
        float o2 = __shfl_xor_sync(FULL, m2, off);
        if (o1 > m1) { m2 = fmaxf(m1, o2); m1 = o1; }
        else         { m2 = fmaxf(m2, o1); }
    }
    float gsum = m1 + m2;

    float gs[8];
    #pragma unroll
    for (int g = 0; g < 8; g++) gs[g] = __shfl_sync(FULL, gsum, g * 4);

    int chosen = 0;
    #pragma unroll
    for (int it = 0; it < 4; it++) {
        float best = -INFINITY; int bg = 0;
        #pragma unroll
        for (int g = 0; g < 8; g++) {
            if (!((chosen >> g) & 1) && gs[g] > best) { best = gs[g]; bg = g; }
        }
        chosen |= 1 << bg;
    }
    const bool kept = (chosen >> (lane >> 2)) & 1;

    float v[8];
    #pragma unroll
    for (int j = 0; j < 8; j++) v[j] = kept ? sb[j] : -INFINITY;

    float my_w = 0.0f; int my_i = 0;
    float wsum = 0.0f;

    #pragma unroll
    for (int it = 0; it < 8; it++) {
        float bv = -INFINITY; int bi = 0x7fffffff; float bsco = 0.0f;
        #pragma unroll
        for (int j = 0; j < 8; j++) {
            if (v[j] > bv) { bv = v[j]; bi = lane * 8 + j; bsco = sc[j]; }
        }
        #pragma unroll
        for (int off = 16; off; off >>= 1) {
            float ov = __shfl_xor_sync(FULL, bv, off);
            int   oi = __shfl_xor_sync(FULL, bi, off);
            float os = __shfl_xor_sync(FULL, bsco, off);
            if (ov > bv || (ov == bv && oi < bi)) { bv = ov; bi = oi; bsco = os; }
        }
        if (lane == it) { my_w = bsco; my_i = bi; }
        if ((bi >> 3) == lane) v[bi & 7] = -INFINITY;
        wsum += bsco;
    }

    if (lane < 8) {
        out_w[(size_t)warp * 8 + lane] = (my_w / wsum) * 2.5f;
        out_i[(size_t)warp * 8 + lane] = (float)my_i;
    }
}

// ---------------------------------------------------------------------------
extern "C" void kernel_launch(void* const* d_in, const int* in_sizes, int n_in,
                              void* d_out, int out_size) {
    const float* x    = (const float*)d_in[0];
    const float* w    = (const float*)d_in[1];
    const float* bias = (const float*)d_in[2];

    const int Tn = in_sizes[0] / KDIM;

    dim3 grid(Tn / BM, NEXP / BN, NSPLIT);
    gate_gemm_kernel<<<grid, 256>>>(x, w);

    float* out_w = (float*)d_out;
    float* out_i = (float*)d_out + (size_t)Tn * 8;

    const int warps_per_block = 8;
    const int blocks = (Tn + warps_per_block - 1) / warps_per_block;
    gate_route_kernel<<<blocks, warps_per_block * 32>>>(bias, out_w, out_i, Tn);
}